// round 9
// baseline (speedup 1.0000x reference)
#include <cuda_runtime.h>
#include <cuda_fp16.h>
#include <cuda_fp8.h>
#include <cstdint>

// ---------------- problem constants ----------------
#define M_IN   16384
#define M_OUT  2048
#define N_DIM  4096
#define K_DIM  4096
#define WORLD  8

// scratch (device-global: no allocations allowed)
__device__ __half g_c [M_OUT * K_DIM];   // 16 MB: pre-reduced quantized activations, K-major
__device__ __half g_wq[N_DIM * K_DIM];   // 32 MB: quantized weight, transposed to [n][k] K-major

// fp8 e4m3 round-trip (RN, satfinite) — exact in fp16
__device__ __forceinline__ float2 fp8rt2(float a, float b) {
    float2 f = make_float2(a, b);
    __nv_fp8x2_storage_t s = __nv_cvt_float2_to_fp8x2(f, __NV_SATFINITE, __NV_E4M3);
    __half2_raw h2r = __nv_cvt_fp8x2_to_halfraw2(s, __NV_E4M3);
    __half2 h2 = *reinterpret_cast<const __half2*>(&h2r);
    return __half22float2(h2);
}

// ---------------- kernel 1: quantize + reduce-scatter-sum (DRAM roofline) ----------------
__global__ void k_reduce_quant(const float* __restrict__ in) {
    int idx4 = blockIdx.x * blockDim.x + threadIdx.x;   // [0, 2048*1024)
    const float4* in4 = (const float4*)in;
    int r = idx4 >> 10;
    int c = idx4 & 1023;
    float sx = 0.f, sy = 0.f, sz = 0.f, sw = 0.f;
    #pragma unroll
    for (int w = 0; w < WORLD; w++) {
        float4 v = in4[(size_t)(w * M_OUT + r) * 1024 + c];
        float2 p0 = fp8rt2(v.x, v.y);
        float2 p1 = fp8rt2(v.z, v.w);
        sx += p0.x; sy += p0.y; sz += p1.x; sw += p1.y;
    }
    __half2* o2 = (__half2*)g_c;
    o2[idx4 * 2 + 0] = __floats2half2_rn(sx, sy);
    o2[idx4 * 2 + 1] = __floats2half2_rn(sz, sw);
}

// ---------------- kernel 2: quantize + transpose weight ----------------
__global__ void k_quant_transpose(const float* __restrict__ w) {
    __shared__ float tile[32][33];
    int tx = threadIdx.x, ty = threadIdx.y;           // 32 x 8
    int k0 = blockIdx.y * 32, n0 = blockIdx.x * 32;
    #pragma unroll
    for (int j = 0; j < 4; j++)
        tile[ty + j * 8][tx] = w[(size_t)(k0 + ty + j * 8) * N_DIM + n0 + tx];
    __syncthreads();
    #pragma unroll
    for (int j = 0; j < 4; j++) {
        int n = n0 + ty + j * 8;
        float2 q = fp8rt2(tile[tx][ty + j * 8], 0.f);
        g_wq[(size_t)n * K_DIM + k0 + tx] = __float2half(q.x);
    }
}

// ---------------- kernel 3: HMMA GEMM 128x256, warp tile 64x64 ----------------
#define BM 128
#define BN 256
#define BKH 32                    // halfs per K stage (64 bytes per row)
#define KT (K_DIM / BKH)          // 128
#define STAGES 3
#define A_BYTES (BM * 64)         // 8192
#define B_BYTES (BN * 64)         // 16384
#define STAGE_BYTES (A_BYTES + B_BYTES)       // 24576
#define SMEM_TOTAL (STAGES * STAGE_BYTES)     // 73728 (needs opt-in)

#define CP16(dst, src) \
    asm volatile("cp.async.cg.shared.global [%0], [%1], 16;" :: "r"(dst), "l"(src))
#define CP_COMMIT() asm volatile("cp.async.commit_group;" ::: "memory")
#define CP_WAIT2()  asm volatile("cp.async.wait_group 2;" ::: "memory")

#define LDSM_X4(r0, r1, r2, r3, addr) \
    asm volatile("ldmatrix.sync.aligned.m8n8.x4.shared.b16 {%0,%1,%2,%3}, [%4];" \
        : "=r"(r0), "=r"(r1), "=r"(r2), "=r"(r3) : "r"(addr) : "memory")

#define MMA16816(d, a, b0, b1) \
    asm volatile("mma.sync.aligned.m16n8k16.row.col.f32.f16.f16.f32 " \
        "{%0,%1,%2,%3}, {%4,%5,%6,%7}, {%8,%9}, {%0,%1,%2,%3};" \
        : "+f"((d)[0]), "+f"((d)[1]), "+f"((d)[2]), "+f"((d)[3]) \
        : "r"((a)[0]), "r"((a)[1]), "r"((a)[2]), "r"((a)[3]), "r"(b0), "r"(b1))

// swizzled byte offset for (row, 16B-chunk c in 0..3) in a [rows x 64B] tile
__device__ __forceinline__ uint32_t swz(int row, int c) {
    return (uint32_t)(row * 64 + ((c ^ ((row >> 1) & 3)) << 4));
}

// fp16-grid round, stored as f32 (reference output values are fp16-representable)
__device__ __forceinline__ float h16(float v) {
    return __half2float(__float2half_rn(v));
}

__global__ void __launch_bounds__(256, 1)
k_gemm(const float* __restrict__ scale_b, float* __restrict__ out)
{
    extern __shared__ char smem[];
    const int tid = threadIdx.x;
    const int wid = tid >> 5, lid = tid & 31;
    const int m0 = blockIdx.y * BM, n0 = blockIdx.x * BN;
    const int wm = wid & 1;        // 2 warps along M (64 rows each)
    const int wn = wid >> 1;       // 4 warps along N (64 cols each)

    uint32_t smem_u = (uint32_t)__cvta_generic_to_shared(smem);
    unsigned long long aG, bG;
    {
        const __half* pa = g_c;
        const __half* pb = g_wq;
        asm("cvta.to.global.u64 %0, %1;" : "=l"(aG) : "l"(pa));
        asm("cvta.to.global.u64 %0, %1;" : "=l"(bG) : "l"(pb));
    }

    float acc[4][8][4];
    #pragma unroll
    for (int i = 0; i < 4; i++)
        #pragma unroll
        for (int j = 0; j < 8; j++)
            #pragma unroll
            for (int k = 0; k < 4; k++) acc[i][j][k] = 0.f;

    // stage loader: A 128 rows + B 256 rows, 4 x 16B chunks each
    auto load_stage = [&](int kt, int buf) {
        uint32_t sA = smem_u + buf * STAGE_BYTES;
        uint32_t sB = sA + A_BYTES;
        #pragma unroll
        for (int i = 0; i < 2; i++) {
            int idx = tid + i * 256;               // 0..511
            int row = idx >> 2, c = idx & 3;
            const char* src = (const char*)(aG +
                ((size_t)(m0 + row) * K_DIM + kt * BKH + c * 8) * 2);
            CP16(sA + swz(row, c), src);
        }
        #pragma unroll
        for (int i = 0; i < 4; i++) {
            int idx = tid + i * 256;               // 0..1023
            int row = idx >> 2, c = idx & 3;
            const char* src = (const char*)(bG +
                ((size_t)(n0 + row) * K_DIM + kt * BKH + c * 8) * 2);
            CP16(sB + swz(row, c), src);
        }
    };

    #pragma unroll
    for (int s = 0; s < STAGES; s++) { load_stage(s, s); CP_COMMIT(); }

    for (int kt = 0; kt < KT; kt++) {
        int buf = kt % STAGES;
        CP_WAIT2();
        __syncthreads();

        uint32_t sA = smem_u + buf * STAGE_BYTES + (wm * 64) * 64;
        uint32_t sB = smem_u + buf * STAGE_BYTES + A_BYTES + (wn * 64) * 64;

        #pragma unroll
        for (int ks = 0; ks < 2; ks++) {          // 2 x k16 per stage
            int c0 = ks * 2;
            uint32_t a[4][4];
            #pragma unroll
            for (int mt = 0; mt < 4; mt++) {
                int row = mt * 16 + (lid & 15);
                int ch  = c0 + (lid >> 4);
                LDSM_X4(a[mt][0], a[mt][1], a[mt][2], a[mt][3], sA + swz(row, ch));
            }
            uint32_t b[4][4];
            #pragma unroll
            for (int p = 0; p < 4; p++) {
                int row = p * 16 + ((lid >> 4) << 3) + (lid & 7);
                int ch  = c0 + ((lid >> 3) & 1);
                LDSM_X4(b[p][0], b[p][1], b[p][2], b[p][3], sB + swz(row, ch));
            }
            #pragma unroll
            for (int mt = 0; mt < 4; mt++)
                #pragma unroll
                for (int nt = 0; nt < 8; nt++) {
                    uint32_t b0 = b[nt >> 1][(nt & 1) * 2];
                    uint32_t b1 = b[nt >> 1][(nt & 1) * 2 + 1];
                    MMA16816(acc[mt][nt], a[mt], b0, b1);
                }
        }
        __syncthreads();
        if (kt + STAGES < KT) load_stage(kt + STAGES, buf);
        CP_COMMIT();
    }

    // ---- epilogue: scale_b, round to fp16 grid, store FLOAT32 ----
    int g = lid >> 2, tg = lid & 3;
    #pragma unroll
    for (int mt = 0; mt < 4; mt++) {
        int row0 = m0 + wm * 64 + mt * 16 + g;
        #pragma unroll
        for (int nt = 0; nt < 8; nt++) {
            int cl = wn * 64 + nt * 8 + tg * 2;
            float2 sc = *(const float2*)(scale_b + n0 + cl);
            int col = n0 + cl;
            *(float2*)(out + (size_t)row0 * N_DIM + col) =
                make_float2(h16(acc[mt][nt][0] * sc.x), h16(acc[mt][nt][1] * sc.y));
            *(float2*)(out + (size_t)(row0 + 8) * N_DIM + col) =
                make_float2(h16(acc[mt][nt][2] * sc.x), h16(acc[mt][nt][3] * sc.y));
        }
    }
}

// ---------------- launch ----------------
extern "C" void kernel_launch(void* const* d_in, const int* in_sizes, int n_in,
                              void* d_out, int out_size) {
    const float* input   = nullptr;   // 16384*4096
    const float* weight  = nullptr;   // 4096*4096
    const float* scale_b = nullptr;   // 4096
    for (int i = 0; i < n_in; i++) {
        if      (in_sizes[i] == M_IN * K_DIM)  input   = (const float*)d_in[i];
        else if (in_sizes[i] == K_DIM * N_DIM) weight  = (const float*)d_in[i];
        else if (in_sizes[i] == N_DIM)         scale_b = (const float*)d_in[i];
    }
    float* out = (float*)d_out;       // [2048, 4096] float32 (fp16 ref upcast)

    static int smem_set = 0;
    if (!smem_set) {
        cudaFuncSetAttribute(k_gemm, cudaFuncAttributeMaxDynamicSharedMemorySize, SMEM_TOTAL);
        smem_set = 1;
    }

    k_reduce_quant<<<(M_OUT * K_DIM / 4) / 256, 256>>>(input);
    k_quant_transpose<<<dim3(N_DIM / 32, K_DIM / 32), dim3(32, 8)>>>(weight);
    k_gemm<<<dim3(N_DIM / BN, M_OUT / BM), 256, SMEM_TOTAL>>>(scale_b, out);
}

// round 17
// speedup vs baseline: 1.1398x; 1.1398x over previous
#include <cuda_runtime.h>
#include <cuda_fp16.h>
#include <cuda_fp8.h>
#include <cstdint>

// ---------------- problem constants ----------------
#define M_IN   16384
#define M_OUT  2048
#define N_DIM  4096
#define K_DIM  4096
#define WORLD  8

// scratch (device-global: no allocations allowed)
__device__ __half g_c [M_OUT * K_DIM];   // 16 MB: pre-reduced quantized activations, K-major
__device__ __half g_wq[N_DIM * K_DIM];   // 32 MB: quantized weight, transposed to [n][k] K-major

// fp8 e4m3 round-trip (RN, satfinite) — exact in fp16
__device__ __forceinline__ float2 fp8rt2(float a, float b) {
    float2 f = make_float2(a, b);
    __nv_fp8x2_storage_t s = __nv_cvt_float2_to_fp8x2(f, __NV_SATFINITE, __NV_E4M3);
    __half2_raw h2r = __nv_cvt_fp8x2_to_halfraw2(s, __NV_E4M3);
    __half2 h2 = *reinterpret_cast<const __half2*>(&h2r);
    return __half22float2(h2);
}

// ---------------- kernel 1: quantize + reduce-scatter-sum (DRAM roofline) ----------------
__global__ void k_reduce_quant(const float* __restrict__ in) {
    int idx4 = blockIdx.x * blockDim.x + threadIdx.x;   // [0, 2048*1024)
    const float4* in4 = (const float4*)in;
    int r = idx4 >> 10;
    int c = idx4 & 1023;
    float sx = 0.f, sy = 0.f, sz = 0.f, sw = 0.f;
    #pragma unroll
    for (int w = 0; w < WORLD; w++) {
        float4 v = in4[(size_t)(w * M_OUT + r) * 1024 + c];
        float2 p0 = fp8rt2(v.x, v.y);
        float2 p1 = fp8rt2(v.z, v.w);
        sx += p0.x; sy += p0.y; sz += p1.x; sw += p1.y;
    }
    __half2* o2 = (__half2*)g_c;
    o2[idx4 * 2 + 0] = __floats2half2_rn(sx, sy);
    o2[idx4 * 2 + 1] = __floats2half2_rn(sz, sw);
}

// ---------------- kernel 2: quantize + transpose weight ----------------
__global__ void k_quant_transpose(const float* __restrict__ w) {
    __shared__ float tile[32][33];
    int tx = threadIdx.x, ty = threadIdx.y;           // 32 x 8
    int k0 = blockIdx.y * 32, n0 = blockIdx.x * 32;
    #pragma unroll
    for (int j = 0; j < 4; j++)
        tile[ty + j * 8][tx] = w[(size_t)(k0 + ty + j * 8) * N_DIM + n0 + tx];
    __syncthreads();
    #pragma unroll
    for (int j = 0; j < 4; j++) {
        int n = n0 + ty + j * 8;
        float2 q = fp8rt2(tile[tx][ty + j * 8], 0.f);
        g_wq[(size_t)n * K_DIM + k0 + tx] = __float2half(q.x);
    }
}

// ---------------- kernel 3: HMMA GEMM 64x128 tiles (fine-grain, balanced) ----------------
#define BM 64
#define BN 128
#define BKH 32                    // halfs per K stage (64 bytes per row)
#define KT (K_DIM / BKH)          // 128
#define STAGES 3
#define A_BYTES (BM * 64)         // 4096
#define B_BYTES (BN * 64)         // 8192
#define STAGE_BYTES (A_BYTES + B_BYTES)       // 12288
#define SMEM_TOTAL (STAGES * STAGE_BYTES)     // 36864 (< 48KB default)
#define GT 128                    // threads per CTA (4 warps, 2x2)

#define CP16(dst, src) \
    asm volatile("cp.async.cg.shared.global [%0], [%1], 16;" :: "r"(dst), "l"(src))
#define CP_COMMIT() asm volatile("cp.async.commit_group;" ::: "memory")
#define CP_WAIT2()  asm volatile("cp.async.wait_group 2;" ::: "memory")

#define LDSM_X4(r0, r1, r2, r3, addr) \
    asm volatile("ldmatrix.sync.aligned.m8n8.x4.shared.b16 {%0,%1,%2,%3}, [%4];" \
        : "=r"(r0), "=r"(r1), "=r"(r2), "=r"(r3) : "r"(addr) : "memory")

#define MMA16816(d, a, b0, b1) \
    asm volatile("mma.sync.aligned.m16n8k16.row.col.f32.f16.f16.f32 " \
        "{%0,%1,%2,%3}, {%4,%5,%6,%7}, {%8,%9}, {%0,%1,%2,%3};" \
        : "+f"((d)[0]), "+f"((d)[1]), "+f"((d)[2]), "+f"((d)[3]) \
        : "r"((a)[0]), "r"((a)[1]), "r"((a)[2]), "r"((a)[3]), "r"(b0), "r"(b1))

// swizzled byte offset for (row, 16B-chunk c in 0..3) in a [rows x 64B] tile
__device__ __forceinline__ uint32_t swz(int row, int c) {
    return (uint32_t)(row * 64 + ((c ^ ((row >> 1) & 3)) << 4));
}

// fp16-grid round, stored as f32 (reference output values are fp16-representable)
__device__ __forceinline__ float h16(float v) {
    return __half2float(__float2half_rn(v));
}

__global__ void __launch_bounds__(GT)
k_gemm(const float* __restrict__ scale_b, float* __restrict__ out)
{
    extern __shared__ char smem[];
    const int tid = threadIdx.x;
    const int wid = tid >> 5, lid = tid & 31;
    const int m0 = blockIdx.y * BM, n0 = blockIdx.x * BN;
    const int wm = wid & 1;        // 2 warps along M (32 rows each)
    const int wn = wid >> 1;       // 2 warps along N (64 cols each)

    uint32_t smem_u = (uint32_t)__cvta_generic_to_shared(smem);
    unsigned long long aG, bG;
    {
        const __half* pa = g_c;
        const __half* pb = g_wq;
        asm("cvta.to.global.u64 %0, %1;" : "=l"(aG) : "l"(pa));
        asm("cvta.to.global.u64 %0, %1;" : "=l"(bG) : "l"(pb));
    }

    float acc[2][8][4];
    #pragma unroll
    for (int i = 0; i < 2; i++)
        #pragma unroll
        for (int j = 0; j < 8; j++)
            #pragma unroll
            for (int k = 0; k < 4; k++) acc[i][j][k] = 0.f;

    // stage loader: A 64 rows + B 128 rows, 4 x 16B chunks each (128 threads)
    auto load_stage = [&](int kt, int buf) {
        uint32_t sA = smem_u + buf * STAGE_BYTES;
        uint32_t sB = sA + A_BYTES;
        #pragma unroll
        for (int i = 0; i < 2; i++) {
            int idx = tid + i * GT;                // 0..255
            int row = idx >> 2, c = idx & 3;
            const char* src = (const char*)(aG +
                ((size_t)(m0 + row) * K_DIM + kt * BKH + c * 8) * 2);
            CP16(sA + swz(row, c), src);
        }
        #pragma unroll
        for (int i = 0; i < 4; i++) {
            int idx = tid + i * GT;                // 0..511
            int row = idx >> 2, c = idx & 3;
            const char* src = (const char*)(bG +
                ((size_t)(n0 + row) * K_DIM + kt * BKH + c * 8) * 2);
            CP16(sB + swz(row, c), src);
        }
    };

    #pragma unroll
    for (int s = 0; s < STAGES; s++) { load_stage(s, s); CP_COMMIT(); }

    for (int kt = 0; kt < KT; kt++) {
        int buf = kt % STAGES;
        CP_WAIT2();
        __syncthreads();

        uint32_t sA = smem_u + buf * STAGE_BYTES + (wm * 32) * 64;
        uint32_t sB = smem_u + buf * STAGE_BYTES + A_BYTES + (wn * 64) * 64;

        #pragma unroll
        for (int ks = 0; ks < 2; ks++) {          // 2 x k16 per stage
            int c0 = ks * 2;
            uint32_t a[2][4];
            #pragma unroll
            for (int mt = 0; mt < 2; mt++) {
                int row = mt * 16 + (lid & 15);
                int ch  = c0 + (lid >> 4);
                LDSM_X4(a[mt][0], a[mt][1], a[mt][2], a[mt][3], sA + swz(row, ch));
            }
            uint32_t b[4][4];
            #pragma unroll
            for (int p = 0; p < 4; p++) {
                int row = p * 16 + ((lid >> 4) << 3) + (lid & 7);
                int ch  = c0 + ((lid >> 3) & 1);
                LDSM_X4(b[p][0], b[p][1], b[p][2], b[p][3], sB + swz(row, ch));
            }
            #pragma unroll
            for (int mt = 0; mt < 2; mt++)
                #pragma unroll
                for (int nt = 0; nt < 8; nt++) {
                    uint32_t b0 = b[nt >> 1][(nt & 1) * 2];
                    uint32_t b1 = b[nt >> 1][(nt & 1) * 2 + 1];
                    MMA16816(acc[mt][nt], a[mt], b0, b1);
                }
        }
        __syncthreads();
        if (kt + STAGES < KT) load_stage(kt + STAGES, buf);
        CP_COMMIT();
    }

    // ---- epilogue: scale_b, round to fp16 grid, store FLOAT32 ----
    int g = lid >> 2, tg = lid & 3;
    #pragma unroll
    for (int mt = 0; mt < 2; mt++) {
        int row0 = m0 + wm * 32 + mt * 16 + g;
        #pragma unroll
        for (int nt = 0; nt < 8; nt++) {
            int cl = wn * 64 + nt * 8 + tg * 2;
            float2 sc = *(const float2*)(scale_b + n0 + cl);
            int col = n0 + cl;
            *(float2*)(out + (size_t)row0 * N_DIM + col) =
                make_float2(h16(acc[mt][nt][0] * sc.x), h16(acc[mt][nt][1] * sc.y));
            *(float2*)(out + (size_t)(row0 + 8) * N_DIM + col) =
                make_float2(h16(acc[mt][nt][2] * sc.x), h16(acc[mt][nt][3] * sc.y));
        }
    }
}

// ---------------- launch ----------------
extern "C" void kernel_launch(void* const* d_in, const int* in_sizes, int n_in,
                              void* d_out, int out_size) {
    const float* input   = nullptr;   // 16384*4096
    const float* weight  = nullptr;   // 4096*4096
    const float* scale_b = nullptr;   // 4096
    for (int i = 0; i < n_in; i++) {
        if      (in_sizes[i] == M_IN * K_DIM)  input   = (const float*)d_in[i];
        else if (in_sizes[i] == K_DIM * N_DIM) weight  = (const float*)d_in[i];
        else if (in_sizes[i] == N_DIM)         scale_b = (const float*)d_in[i];
    }
    float* out = (float*)d_out;       // [2048, 4096] float32 (fp16 ref upcast)

    k_reduce_quant<<<(M_OUT * K_DIM / 4) / 256, 256>>>(input);
    k_quant_transpose<<<dim3(N_DIM / 32, K_DIM / 32), dim3(32, 8)>>>(weight);
    k_gemm<<<dim3(N_DIM / BN, M_OUT / BM), GT, SMEM_TOTAL>>>(scale_b, out);
}